// round 16
// baseline (speedup 1.0000x reference)
#include <cuda_runtime.h>
#include <cuda_fp16.h>
#include <cstdint>

// Problem constants
#define Bb 2
#define Cc 256
#define Hh 128
#define Ww 128
#define Oo 256
#define HW 16384            // H*W
#define OFFC 72
#define NCH3 12             // merged chunks: 3 flat (g,tap) subs, K=192
#define SROW 400            // S row stride bytes (192c*2B data + 16B pad)
#define SB2 (64 * SROW)     // S buffer bytes (25600)
#define XPW 129             // padded pair-row width
#define NQ 64               // channel quads per batch image
#define WFN (36 * 8 * 4 * 2 * 32 * 4)   // u32 count of fragment-packed W

// fat-prep dispatch ranges (256 threads/block)
#define NB_OFF 128                       // offset job blocks
#define NB_WF  (WFN / 256)               // 1152 pack_wf blocks
#define NB_XQ  ((Bb * NQ * Hh * XPW) / 256)   // 8256 pack_q blocks

// Scratch (device globals: allocation-free rule)
__device__ float2 g_off2[Bb * 36 * HW];          // packed (dy,dx) per (b, g*9+tap, pixel)
__device__ uint32_t g_wf[WFN];                   // W pre-packed as mma B-fragments
__device__ uint4 g_xq[Bb * NQ * Hh * XPW];       // 4-channel quad of horizontal pairs per (y,xi)

// ---------------------------------------------------------------------------
// helpers
// ---------------------------------------------------------------------------
__device__ __forceinline__ uint32_t smem_u32(const void* p) {
    uint32_t a;
    asm("{ .reg .u64 t; cvta.to.shared.u64 t, %1; cvt.u32.u64 %0, t; }" : "=r"(a) : "l"(p));
    return a;
}
__device__ __forceinline__ void ldsm4(uint32_t* r, uint32_t addr) {
    asm volatile("ldmatrix.sync.aligned.m8n8.x4.shared.b16 {%0,%1,%2,%3}, [%4];"
                 : "=r"(r[0]), "=r"(r[1]), "=r"(r[2]), "=r"(r[3]) : "r"(addr));
}
__device__ __forceinline__ void mma_f16(float* c, const uint32_t* a, const uint32_t* b) {
    asm volatile(
        "mma.sync.aligned.m16n8k16.row.col.f32.f16.f16.f32 "
        "{%0,%1,%2,%3},{%4,%5,%6,%7},{%8,%9},{%0,%1,%2,%3};"
        : "+f"(c[0]), "+f"(c[1]), "+f"(c[2]), "+f"(c[3])
        : "r"(a[0]), "r"(a[1]), "r"(a[2]), "r"(a[3]), "r"(b[0]), "r"(b[1]));
}
__device__ __forceinline__ void sts128u(uint32_t a, uint32_t x, uint32_t y, uint32_t z, uint32_t w) {
    asm volatile("st.shared.v4.b32 [%0], {%1,%2,%3,%4};" :: "r"(a), "r"(x), "r"(y), "r"(z), "r"(w));
}
// f32x2 packed-FMA helpers
__device__ __forceinline__ void fma2(unsigned long long& d, unsigned long long a,
                                     unsigned long long b) {
    asm("fma.rn.f32x2 %0, %1, %2, %0;" : "+l"(d) : "l"(a), "l"(b));
}
__device__ __forceinline__ void unpack2(unsigned long long r, float& lo, float& hi) {
    asm("mov.b64 {%0, %1}, %2;" : "=f"(lo), "=f"(hi) : "l"(r));
}

// ---------------------------------------------------------------------------
// prep jobs (device functions, dispatched by block range from k_prep)
// ---------------------------------------------------------------------------
__device__ void job_pack_wf(int blk, const float* __restrict__ w) {
    int idx = blk * 256 + threadIdx.x;
    int j4 = idx & 3;
    int l = (idx >> 2) & 31;
    int g = (idx >> 7) & 1;
    int ks = (idx >> 8) & 3;
    int wo = (idx >> 10) & 7;
    int cid = idx >> 13;
    int ni = g * 2 + (j4 >> 1);
    int rj = j4 & 1;
    int o = wo * 32 + ni * 8 + (l >> 2);
    int klo = ks * 16 + (l & 3) * 2 + rj * 8;
    int g4 = cid / 9;
    int tap = cid - g4 * 9;
    int c0 = g4 * 64 + klo;
    float f0 = __ldg(&w[((size_t)o * Cc + c0) * 9 + tap]);
    float f1 = __ldg(&w[((size_t)o * Cc + c0 + 1) * 9 + tap]);
    __half2 hh = __floats2half2_rn(f0, f1);
    g_wf[idx] = *(uint32_t*)&hh;
}

__device__ void job_pack_q(int blk, const float* __restrict__ x) {
    int idx = blk * 256 + threadIdx.x;
    int xi = idx % XPW;
    int rest = idx / XPW;         // (b*NQ+q)*Hh + y
    int y = rest & 127;
    int bq = rest >> 7;
    int q = bq & (NQ - 1);
    int b = bq >> 6;
    const float* src = x + ((size_t)(b * Cc + q * 4) * Hh + y) * Ww;
    uint32_t u[4];
#pragma unroll
    for (int j = 0; j < 4; ++j) {
        const float* s = src + (size_t)j * HW;
        float lo = (xi >= 1) ? __ldg(s + xi - 1) : 0.f;
        float hi = (xi <= 127) ? __ldg(s + xi) : 0.f;
        __half2 hh = __floats2half2_rn(lo, hi);
        u[j] = *(uint32_t*)&hh;
    }
    g_xq[idx] = make_uint4(u[0], u[1], u[2], u[3]);
}

__device__ void job_offset(int blk, const float* __restrict__ x,
                           const float* __restrict__ w_off,
                           const float* __restrict__ b_off, float* ws) {
    for (int i = threadIdx.x; i < OFFC * Cc; i += 256) {
        int o = i / Cc, c = i % Cc;
        ws[c * OFFC + o] = w_off[i];
    }
    __syncthreads();

    const int team = threadIdx.x >> 1;
    const int oh = threadIdx.x & 1;
    int pix0 = blk * 256 + team * 2;
    int b = pix0 >> 14;
    int hw = pix0 & (HW - 1);
    const float* xp = x + (size_t)b * Cc * HW + hw;

    unsigned long long acc[2][18];
#pragma unroll
    for (int i = 0; i < 18; i++) {
        unsigned long long bb = ((const unsigned long long*)b_off)[oh * 18 + i];
        acc[0][i] = bb;
        acc[1][i] = bb;
    }

    for (int c = 0; c < Cc; c++) {
        float2 v = __ldg((const float2*)&xp[(size_t)c * HW]);
        unsigned long long v0, v1;
        asm("mov.b64 %0, {%1, %1};" : "=l"(v0) : "f"(v.x));
        asm("mov.b64 %0, {%1, %1};" : "=l"(v1) : "f"(v.y));
        const float4* wrow = (const float4*)&ws[c * OFFC + oh * 36];
#pragma unroll
        for (int i = 0; i < 9; i++) {
            float4 w4 = wrow[i];
            unsigned long long w01, w23;
            asm("mov.b64 %0, {%1, %2};" : "=l"(w01) : "f"(w4.x), "f"(w4.y));
            asm("mov.b64 %0, {%1, %2};" : "=l"(w23) : "f"(w4.z), "f"(w4.w));
            fma2(acc[0][i * 2], v0, w01);
            fma2(acc[0][i * 2 + 1], v0, w23);
            fma2(acc[1][i * 2], v1, w01);
            fma2(acc[1][i * 2 + 1], v1, w23);
        }
    }
#pragma unroll
    for (int px = 0; px < 2; ++px) {
        float* op = (float*)(g_off2 + (size_t)b * 36 * HW);
#pragma unroll
        for (int i = 0; i < 18; i++) {
            float lo, hi;
            unpack2(acc[px][i], lo, hi);
            int q0 = oh * 36 + i * 2;
            int p0 = q0 >> 1;
            op[((size_t)p0 * HW + hw + px) * 2 + (q0 & 1)] = lo;
            int q1 = q0 + 1;
            int p1 = q1 >> 1;
            op[((size_t)p1 * HW + hw + px) * 2 + (q1 & 1)] = hi;
        }
    }
}

// ---------------------------------------------------------------------------
// K_PREP: fat kernel — all three independent prep jobs run concurrently.
// blocks [0,128): offset; [128,1280): pack_wf; [1280,9536): pack_q.
// ---------------------------------------------------------------------------
__global__ __launch_bounds__(256) void k_prep(const float* __restrict__ x,
                                              const float* __restrict__ w_off,
                                              const float* __restrict__ b_off,
                                              const float* __restrict__ w_def) {
    extern __shared__ float ws[];
    int bx = blockIdx.x;
    if (bx < NB_OFF) {
        job_offset(bx, x, w_off, b_off, ws);
    } else if (bx < NB_OFF + NB_WF) {
        job_pack_wf(bx - NB_OFF, w_def);
    } else {
        job_pack_q(bx - NB_OFF - NB_WF, x);
    }
}

// ---------------------------------------------------------------------------
// K2: fused deformable conv + ReLU, fp16 mma.sync m16n8k16, fp32 accum.
// EXACT R14 version: CTA = 64p x 256o, 256 thr, 2 CTA/SM; 12 merged K-chunks
// of 192c with register-light staging; 8 warps x (64p x 32o), full K each.
// ---------------------------------------------------------------------------
__global__ __launch_bounds__(256, 2) void k_deform(float* __restrict__ out) {
    extern __shared__ float dsm[];
    const uint32_t base = smem_u32(dsm);
    const uint32_t sSb[2] = {base, base + SB2};

    const int bx = blockIdx.x;
    const int pseg = bx & 1;
    const int h = (bx >> 1) & 127;
    const int b = bx >> 8;
    const int w0 = pseg * 64;
    const int tid = threadIdx.x;
    const int lid = tid & 31;
    const int wo = tid >> 5;       // o-slice (32o) of this warp

    const uint32_t a_row16 = lid & 15;
    const uint32_t a_csel = lid >> 4;

    float acc[4][4][4];
#pragma unroll
    for (int i = 0; i < 4; i++)
#pragma unroll
        for (int j = 0; j < 4; j++)
#pragma unroll
            for (int k = 0; k < 4; k++) acc[i][j][k] = 0.f;

    const int sp = tid & 63;       // pixel within the 64-tile
    const int cq = tid >> 6;       // 0..3: 16-channel slice of each 64c sub
    const int wpix = w0 + sp;

    auto sample = [&](int f, uint32_t* v8) {
        const int g = f / 9;
        const int tap = f - g * 9;
        const float2 od = __ldg(&g_off2[((size_t)b * 36 + f) * HW + h * Ww + wpix]);
        float ys = (float)(h - 1 + tap / 3) + od.x;
        float xs = (float)(wpix - 1 + tap % 3) + od.y;
        float y0f = floorf(ys), x0f = floorf(xs);
        float ly = ys - y0f, lx = xs - x0f;
        int y0 = (int)y0f;
        int xi = (int)x0f + 1;

        float wy0 = (y0 >= 0 && y0 < Hh) ? (1.f - ly) : 0.f;
        float wy1 = (y0 >= -1 && y0 < Hh - 1) ? ly : 0.f;
        bool okx = (xi >= 0 && xi <= Ww);
        float wl = okx ? (1.f - lx) : 0.f;
        float wh = okx ? lx : 0.f;
        int y0c = min(max(y0, 0), Hh - 1);
        int y1c = min(max(y0 + 1, 0), Hh - 1);
        int xic = min(max(xi, 0), Ww);

        const int qbase = (b * NQ + g * 16 + cq * 4);
#pragma unroll
        for (int jj = 0; jj < 4; ++jj) {
            const uint4* rowb = g_xq + (size_t)(qbase + jj) * (Hh * XPW);
            uint4 l0 = __ldg(rowb + y0c * XPW + xic);
            uint4 l1 = __ldg(rowb + y1c * XPW + xic);
            float s[4];
            const uint32_t* u0 = (const uint32_t*)&l0;
            const uint32_t* u1 = (const uint32_t*)&l1;
#pragma unroll
            for (int j = 0; j < 4; ++j) {
                float2 a = __half22float2(*(const __half2*)&u0[j]);
                float2 bb = __half22float2(*(const __half2*)&u1[j]);
                s[j] = (a.x * wl + a.y * wh) * wy0 + (bb.x * wl + bb.y * wh) * wy1;
            }
            __half2 h0 = __floats2half2_rn(s[0], s[1]);
            __half2 h1 = __floats2half2_rn(s[2], s[3]);
            v8[jj * 2] = *(uint32_t*)&h0;
            v8[jj * 2 + 1] = *(uint32_t*)&h1;
        }
    };

    const uint32_t s_row = (uint32_t)(sp * SROW) + cq * 32u;

    auto stage = [&](int t, uint32_t dstb) {
#pragma unroll
        for (int s = 0; s < 3; ++s) {
            uint32_t v8[8];
            sample(3 * t + s, v8);
            uint32_t a = dstb + s_row + (uint32_t)(s * 128);
            sts128u(a, v8[0], v8[1], v8[2], v8[3]);
            sts128u(a + 16u, v8[4], v8[5], v8[6], v8[7]);
        }
    };

    const uint4* wf4 = (const uint4*)g_wf;
    auto load_bq = [&](int t, int ks, uint4* dst) {
        int cidf = 3 * t + (ks >> 2);
        int ko = ks & 3;
#pragma unroll
        for (int g = 0; g < 2; ++g)
            dst[g] = __ldg(wf4 + ((size_t)((cidf * 8 + wo) * 4 + ko) * 2 + g) * 32 + lid);
    };

    stage(0, sSb[0]);

    for (int t = 0; t < NCH3; ++t) {
        const int buf = t & 1;

        __syncthreads();  // publishes S(t); gemm(t-1) done with buf^1

        uint4 bq[2][2];
        load_bq(t, 0, bq[0]);

        if (t + 1 < NCH3)
            stage(t + 1, sSb[buf ^ 1]);   // gather latency hides under gemm(t)

#pragma unroll
        for (int ks = 0; ks < 12; ++ks) {
            if (ks + 1 < 12) load_bq(t, ks + 1, bq[(ks + 1) & 1]);
            const uint32_t coff = (uint32_t)((ks >> 2) * 128 + ((ks & 3) * 2 + a_csel) * 16);
            uint32_t afr[4][4];
#pragma unroll
            for (int mi = 0; mi < 4; ++mi) {
                uint32_t row = (uint32_t)(mi * 16) + a_row16;
                ldsm4(afr[mi], sSb[buf] + row * SROW + coff);
            }
            const uint32_t* b0 = (const uint32_t*)&bq[ks & 1][0];
            const uint32_t* b1 = (const uint32_t*)&bq[ks & 1][1];
#pragma unroll
            for (int mi = 0; mi < 4; ++mi) {
                mma_f16(acc[mi][0], afr[mi], b0);
                mma_f16(acc[mi][1], afr[mi], b0 + 2);
                mma_f16(acc[mi][2], afr[mi], b1);
                mma_f16(acc[mi][3], afr[mi], b1 + 2);
            }
        }
    }

    // --- epilogue: ReLU + store ---
    {
        const int gq = lid >> 2;
        const int tq = lid & 3;
#pragma unroll
        for (int mi = 0; mi < 4; ++mi) {
#pragma unroll
            for (int ni = 0; ni < 4; ++ni) {
                int o = wo * 32 + ni * 8 + 2 * tq;
                int p = w0 + mi * 16 + gq;
                float* op = out + ((size_t)(b * Oo + o)) * HW + h * Ww + p;
                op[0] = fmaxf(acc[mi][ni][0], 0.f);
                op[HW] = fmaxf(acc[mi][ni][1], 0.f);
                op[8] = fmaxf(acc[mi][ni][2], 0.f);
                op[HW + 8] = fmaxf(acc[mi][ni][3], 0.f);
            }
        }
    }
}

// ---------------------------------------------------------------------------
extern "C" void kernel_launch(void* const* d_in, const int* in_sizes, int n_in,
                              void* d_out, int out_size) {
    const float* x = (const float*)d_in[0];        // [2,256,128,128]
    const float* w_off = (const float*)d_in[1];    // [72,256,1,1]
    const float* b_off = (const float*)d_in[2];    // [72]
    const float* w_def = (const float*)d_in[3];    // [256,256,3,3]
    float* out = (float*)d_out;

    const int OFF_SMEM = OFFC * Cc * sizeof(float);   // 73728
    const int DEF_SMEM = 2 * SB2;                     // 51200

    cudaFuncSetAttribute(k_prep, cudaFuncAttributeMaxDynamicSharedMemorySize, OFF_SMEM);
    cudaFuncSetAttribute(k_deform, cudaFuncAttributeMaxDynamicSharedMemorySize, DEF_SMEM);

    k_prep<<<NB_OFF + NB_WF + NB_XQ, 256, OFF_SMEM>>>(x, w_off, b_off, w_def);
    k_deform<<<Bb * Hh * 2, 256, DEF_SMEM>>>(out);
}

// round 17
// speedup vs baseline: 1.1023x; 1.1023x over previous
#include <cuda_runtime.h>
#include <cuda_fp16.h>
#include <cstdint>

// Problem constants
#define Bb 2
#define Cc 256
#define Hh 128
#define Ww 128
#define Oo 256
#define HW 16384            // H*W
#define OFFC 72
#define NCH3 12             // merged chunks: 3 flat (g,tap) subs, K=192
#define SROW 400            // S row stride bytes (192c*2B data + 16B pad)
#define SB2 (64 * SROW)     // S buffer bytes (25600)
#define XPW 129             // padded pair-row width
#define NQ 64               // channel quads per batch image
#define WFN (36 * 8 * 4 * 2 * 32 * 4)   // u32 count of fragment-packed W

// Scratch (device globals: allocation-free rule)
__device__ float2 g_off2[Bb * 36 * HW];          // packed (dy,dx) per (b, g*9+tap, pixel)
__device__ uint32_t g_wf[WFN];                   // W pre-packed as mma B-fragments
__device__ uint4 g_xq[Bb * NQ * Hh * XPW];       // 4-channel quad of horizontal pairs per (y,xi)

// ---------------------------------------------------------------------------
// helpers
// ---------------------------------------------------------------------------
__device__ __forceinline__ uint32_t smem_u32(const void* p) {
    uint32_t a;
    asm("{ .reg .u64 t; cvta.to.shared.u64 t, %1; cvt.u32.u64 %0, t; }" : "=r"(a) : "l"(p));
    return a;
}
__device__ __forceinline__ void ldsm4(uint32_t* r, uint32_t addr) {
    asm volatile("ldmatrix.sync.aligned.m8n8.x4.shared.b16 {%0,%1,%2,%3}, [%4];"
                 : "=r"(r[0]), "=r"(r[1]), "=r"(r[2]), "=r"(r[3]) : "r"(addr));
}
__device__ __forceinline__ void mma_f16(float* c, const uint32_t* a, const uint32_t* b) {
    asm volatile(
        "mma.sync.aligned.m16n8k16.row.col.f32.f16.f16.f32 "
        "{%0,%1,%2,%3},{%4,%5,%6,%7},{%8,%9},{%0,%1,%2,%3};"
        : "+f"(c[0]), "+f"(c[1]), "+f"(c[2]), "+f"(c[3])
        : "r"(a[0]), "r"(a[1]), "r"(a[2]), "r"(a[3]), "r"(b[0]), "r"(b[1]));
}
__device__ __forceinline__ void sts128u(uint32_t a, uint32_t x, uint32_t y, uint32_t z, uint32_t w) {
    asm volatile("st.shared.v4.b32 [%0], {%1,%2,%3,%4};" :: "r"(a), "r"(x), "r"(y), "r"(z), "r"(w));
}
// f32x2 packed-FMA helpers
__device__ __forceinline__ void fma2(unsigned long long& d, unsigned long long a,
                                     unsigned long long b) {
    asm("fma.rn.f32x2 %0, %1, %2, %0;" : "+l"(d) : "l"(a), "l"(b));
}
__device__ __forceinline__ void unpack2(unsigned long long r, float& lo, float& hi) {
    asm("mov.b64 {%0, %1}, %2;" : "=f"(lo), "=f"(hi) : "l"(r));
}

// ---------------------------------------------------------------------------
// K0a: pack deform weights into m16n8k16 B-fragment layout (fp16). (R12/R14)
// ---------------------------------------------------------------------------
__global__ void k_pack_wf(const float* __restrict__ w) {
    int idx = blockIdx.x * blockDim.x + threadIdx.x;
    if (idx >= WFN) return;
    int j4 = idx & 3;
    int l = (idx >> 2) & 31;
    int g = (idx >> 7) & 1;
    int ks = (idx >> 8) & 3;
    int wo = (idx >> 10) & 7;
    int cid = idx >> 13;
    int ni = g * 2 + (j4 >> 1);
    int rj = j4 & 1;
    int o = wo * 32 + ni * 8 + (l >> 2);
    int klo = ks * 16 + (l & 3) * 2 + rj * 8;
    int g4 = cid / 9;
    int tap = cid - g4 * 9;
    int c0 = g4 * 64 + klo;
    float f0 = __ldg(&w[((size_t)o * Cc + c0) * 9 + tap]);
    float f1 = __ldg(&w[((size_t)o * Cc + c0 + 1) * 9 + tap]);
    __half2 hh = __floats2half2_rn(f0, f1);
    g_wf[idx] = *(uint32_t*)&hh;
}

// ---------------------------------------------------------------------------
// K0b: pack x into 4-channel quads of fp16 horizontal pairs. (R12/R14)
// ---------------------------------------------------------------------------
__global__ void k_pack_q(const float* __restrict__ x) {
    int idx = blockIdx.x * blockDim.x + threadIdx.x;
    if (idx >= Bb * NQ * Hh * XPW) return;
    int xi = idx % XPW;
    int rest = idx / XPW;         // (b*NQ+q)*Hh + y
    int y = rest & 127;
    int bq = rest >> 7;
    int q = bq & (NQ - 1);
    int b = bq >> 6;
    const float* src = x + ((size_t)(b * Cc + q * 4) * Hh + y) * Ww;
    uint32_t u[4];
#pragma unroll
    for (int j = 0; j < 4; ++j) {
        const float* s = src + (size_t)j * HW;
        float lo = (xi >= 1) ? __ldg(s + xi - 1) : 0.f;
        float hi = (xi <= 127) ? __ldg(s + xi) : 0.f;
        __half2 hh = __floats2half2_rn(lo, hi);
        u[j] = *(uint32_t*)&hh;
    }
    g_xq[idx] = make_uint4(u[0], u[1], u[2], u[3]);
}

// ---------------------------------------------------------------------------
// K1 v2: offset matvec. 1 pixel/thread, o-half split (36 outputs, 18 u64 acc),
// weights staged in TWO 128-channel passes (36KB smem) -> 256 blocks, all SMs
// busy, up to 4 blocks/SM. Same fp32 math as R14's k_offset.
// ---------------------------------------------------------------------------
__global__ __launch_bounds__(256) void k_offset(const float* __restrict__ x,
                                                const float* __restrict__ w_off,
                                                const float* __restrict__ b_off) {
    extern __shared__ float ws[];  // [128 c][72 o], c-local major

    const int tid = threadIdx.x;
    const int oh = tid & 1;             // o-half (36 outputs)
    const int pxl = tid >> 1;           // 0..127 local pixel
    int pix = blockIdx.x * 128 + pxl;   // 0..32767
    int b = pix >> 14;
    int hw = pix & (HW - 1);
    const float* xp = x + (size_t)b * Cc * HW + hw;

    unsigned long long acc[18];
#pragma unroll
    for (int i = 0; i < 18; i++)
        acc[i] = ((const unsigned long long*)b_off)[oh * 18 + i];

#pragma unroll
    for (int pass = 0; pass < 2; ++pass) {
        __syncthreads();   // previous pass's reads done
        for (int i = tid; i < 128 * OFFC; i += 256) {
            int o = i / 128;
            int cl = i - o * 128;
            ws[cl * OFFC + o] = w_off[o * Cc + pass * 128 + cl];
        }
        __syncthreads();

        const float* xpp = xp + (size_t)(pass * 128) * HW;
        for (int cl = 0; cl < 128; ++cl) {
            float v = __ldg(&xpp[(size_t)cl * HW]);
            unsigned long long vv;
            asm("mov.b64 %0, {%1, %1};" : "=l"(vv) : "f"(v));
            const float4* wrow = (const float4*)&ws[cl * OFFC + oh * 36];
#pragma unroll
            for (int i = 0; i < 9; i++) {
                float4 w4 = wrow[i];
                unsigned long long w01, w23;
                asm("mov.b64 %0, {%1, %2};" : "=l"(w01) : "f"(w4.x), "f"(w4.y));
                asm("mov.b64 %0, {%1, %2};" : "=l"(w23) : "f"(w4.z), "f"(w4.w));
                fma2(acc[i * 2], vv, w01);
                fma2(acc[i * 2 + 1], vv, w23);
            }
        }
    }

    // outputs: q = oh*36 + 2j (+1); both land in plane p = oh*18 + j as (dy,dx)
    float2* op = g_off2 + (size_t)b * 36 * HW + hw;
#pragma unroll
    for (int j = 0; j < 18; j++) {
        float lo, hi;
        unpack2(acc[j], lo, hi);
        op[(size_t)(oh * 18 + j) * HW] = make_float2(lo, hi);
    }
}

// ---------------------------------------------------------------------------
// K2: fused deformable conv + ReLU, fp16 mma.sync m16n8k16, fp32 accum.
// EXACT R14 version (best: 156.2us).
// ---------------------------------------------------------------------------
__global__ __launch_bounds__(256, 2) void k_deform(float* __restrict__ out) {
    extern __shared__ float dsm[];
    const uint32_t base = smem_u32(dsm);
    const uint32_t sSb[2] = {base, base + SB2};

    const int bx = blockIdx.x;
    const int pseg = bx & 1;
    const int h = (bx >> 1) & 127;
    const int b = bx >> 8;
    const int w0 = pseg * 64;
    const int tid = threadIdx.x;
    const int lid = tid & 31;
    const int wo = tid >> 5;       // o-slice (32o) of this warp

    const uint32_t a_row16 = lid & 15;
    const uint32_t a_csel = lid >> 4;

    float acc[4][4][4];
#pragma unroll
    for (int i = 0; i < 4; i++)
#pragma unroll
        for (int j = 0; j < 4; j++)
#pragma unroll
            for (int k = 0; k < 4; k++) acc[i][j][k] = 0.f;

    const int sp = tid & 63;       // pixel within the 64-tile
    const int cq = tid >> 6;       // 0..3: 16-channel slice of each 64c sub
    const int wpix = w0 + sp;

    auto sample = [&](int f, uint32_t* v8) {
        const int g = f / 9;
        const int tap = f - g * 9;
        const float2 od = __ldg(&g_off2[((size_t)b * 36 + f) * HW + h * Ww + wpix]);
        float ys = (float)(h - 1 + tap / 3) + od.x;
        float xs = (float)(wpix - 1 + tap % 3) + od.y;
        float y0f = floorf(ys), x0f = floorf(xs);
        float ly = ys - y0f, lx = xs - x0f;
        int y0 = (int)y0f;
        int xi = (int)x0f + 1;

        float wy0 = (y0 >= 0 && y0 < Hh) ? (1.f - ly) : 0.f;
        float wy1 = (y0 >= -1 && y0 < Hh - 1) ? ly : 0.f;
        bool okx = (xi >= 0 && xi <= Ww);
        float wl = okx ? (1.f - lx) : 0.f;
        float wh = okx ? lx : 0.f;
        int y0c = min(max(y0, 0), Hh - 1);
        int y1c = min(max(y0 + 1, 0), Hh - 1);
        int xic = min(max(xi, 0), Ww);

        const int qbase = (b * NQ + g * 16 + cq * 4);
#pragma unroll
        for (int jj = 0; jj < 4; ++jj) {
            const uint4* rowb = g_xq + (size_t)(qbase + jj) * (Hh * XPW);
            uint4 l0 = __ldg(rowb + y0c * XPW + xic);
            uint4 l1 = __ldg(rowb + y1c * XPW + xic);
            float s[4];
            const uint32_t* u0 = (const uint32_t*)&l0;
            const uint32_t* u1 = (const uint32_t*)&l1;
#pragma unroll
            for (int j = 0; j < 4; ++j) {
                float2 a = __half22float2(*(const __half2*)&u0[j]);
                float2 bb = __half22float2(*(const __half2*)&u1[j]);
                s[j] = (a.x * wl + a.y * wh) * wy0 + (bb.x * wl + bb.y * wh) * wy1;
            }
            __half2 h0 = __floats2half2_rn(s[0], s[1]);
            __half2 h1 = __floats2half2_rn(s[2], s[3]);
            v8[jj * 2] = *(uint32_t*)&h0;
            v8[jj * 2 + 1] = *(uint32_t*)&h1;
        }
    };

    const uint32_t s_row = (uint32_t)(sp * SROW) + cq * 32u;

    auto stage = [&](int t, uint32_t dstb) {
#pragma unroll
        for (int s = 0; s < 3; ++s) {
            uint32_t v8[8];
            sample(3 * t + s, v8);
            uint32_t a = dstb + s_row + (uint32_t)(s * 128);
            sts128u(a, v8[0], v8[1], v8[2], v8[3]);
            sts128u(a + 16u, v8[4], v8[5], v8[6], v8[7]);
        }
    };

    const uint4* wf4 = (const uint4*)g_wf;
    auto load_bq = [&](int t, int ks, uint4* dst) {
        int cidf = 3 * t + (ks >> 2);
        int ko = ks & 3;
#pragma unroll
        for (int g = 0; g < 2; ++g)
            dst[g] = __ldg(wf4 + ((size_t)((cidf * 8 + wo) * 4 + ko) * 2 + g) * 32 + lid);
    };

    stage(0, sSb[0]);

    for (int t = 0; t < NCH3; ++t) {
        const int buf = t & 1;

        __syncthreads();  // publishes S(t); gemm(t-1) done with buf^1

        uint4 bq[2][2];
        load_bq(t, 0, bq[0]);

        if (t + 1 < NCH3)
            stage(t + 1, sSb[buf ^ 1]);   // gather latency hides under gemm(t)

#pragma unroll
        for (int ks = 0; ks < 12; ++ks) {
            if (ks + 1 < 12) load_bq(t, ks + 1, bq[(ks + 1) & 1]);
            const uint32_t coff = (uint32_t)((ks >> 2) * 128 + ((ks & 3) * 2 + a_csel) * 16);
            uint32_t afr[4][4];
#pragma unroll
            for (int mi = 0; mi < 4; ++mi) {
                uint32_t row = (uint32_t)(mi * 16) + a_row16;
                ldsm4(afr[mi], sSb[buf] + row * SROW + coff);
            }
            const uint32_t* b0 = (const uint32_t*)&bq[ks & 1][0];
            const uint32_t* b1 = (const uint32_t*)&bq[ks & 1][1];
#pragma unroll
            for (int mi = 0; mi < 4; ++mi) {
                mma_f16(acc[mi][0], afr[mi], b0);
                mma_f16(acc[mi][1], afr[mi], b0 + 2);
                mma_f16(acc[mi][2], afr[mi], b1);
                mma_f16(acc[mi][3], afr[mi], b1 + 2);
            }
        }
    }

    // --- epilogue: ReLU + store ---
    {
        const int gq = lid >> 2;
        const int tq = lid & 3;
#pragma unroll
        for (int mi = 0; mi < 4; ++mi) {
#pragma unroll
            for (int ni = 0; ni < 4; ++ni) {
                int o = wo * 32 + ni * 8 + 2 * tq;
                int p = w0 + mi * 16 + gq;
                float* op = out + ((size_t)(b * Oo + o)) * HW + h * Ww + p;
                op[0] = fmaxf(acc[mi][ni][0], 0.f);
                op[HW] = fmaxf(acc[mi][ni][1], 0.f);
                op[8] = fmaxf(acc[mi][ni][2], 0.f);
                op[HW + 8] = fmaxf(acc[mi][ni][3], 0.f);
            }
        }
    }
}

// ---------------------------------------------------------------------------
extern "C" void kernel_launch(void* const* d_in, const int* in_sizes, int n_in,
                              void* d_out, int out_size) {
    const float* x = (const float*)d_in[0];        // [2,256,128,128]
    const float* w_off = (const float*)d_in[1];    // [72,256,1,1]
    const float* b_off = (const float*)d_in[2];    // [72]
    const float* w_def = (const float*)d_in[3];    // [256,256,3,3]
    float* out = (float*)d_out;

    const int OFF_SMEM = 128 * OFFC * sizeof(float);  // 36864 (two-pass staging)
    const int DEF_SMEM = 2 * SB2;                     // 51200

    cudaFuncSetAttribute(k_offset, cudaFuncAttributeMaxDynamicSharedMemorySize, OFF_SMEM);
    cudaFuncSetAttribute(k_deform, cudaFuncAttributeMaxDynamicSharedMemorySize, DEF_SMEM);

    k_pack_wf<<<(WFN + 255) / 256, 256>>>(w_def);
    k_pack_q<<<(Bb * NQ * Hh * XPW + 255) / 256, 256>>>(x);
    k_offset<<<(Bb * HW) / 128, 256, OFF_SMEM>>>(x, w_off, b_off);
    k_deform<<<Bb * Hh * 2, 256, DEF_SMEM>>>(out);
}